// round 6
// baseline (speedup 1.0000x reference)
#include <cuda_runtime.h>
#include <cstdint>
#include <cstddef>

// ---------------------------------------------------------------------------
// 2-layer LSTM (T=512, B=4096, D=64, H=70) + MLP head.
// R5: input GEMMs (x @ Wih^T + bias) precomputed for the whole sequence as
//     parallel GEMMs (both layers); serial recurrence runs only k=70.
//     Gate-init streamed from gx with double-buffered LDG. MUFU activations.
// ---------------------------------------------------------------------------

#define TT   512
#define BB   4096
#define DD   64
#define HH   70
#define GP   288          // padded gate cols (4*72), col = 4n + gate
#define BC   32           // batch rows per recurrence CTA
#define NBLK (BB / BC)    // 128 blocks
#define NTHR 256

typedef unsigned long long u64;

// scratch: gate-x buffer [T][288][B] (reused for both layers),
//          h0 sequence [T][70][B], final h1 [70][B]
__device__ float g_gx[(size_t)TT * GP * BB];
__device__ float g_h0[(size_t)TT * HH * BB];
__device__ float g_h1[HH * BB];

#define FMA2A(d, a, b) \
    asm("fma.rn.f32x2 %0, %1, %2, %0;" : "+l"(d) : "l"(a), "l"(b))

__device__ __forceinline__ u64 dup2(float v) {
    u64 r;
    unsigned int u = __float_as_uint(v);
    asm("mov.b64 %0, {%1,%2};" : "=l"(r) : "r"(u), "r"(u));
    return r;
}
__device__ __forceinline__ u64 pack2f(float lo, float hi) {
    u64 r;
    asm("mov.b64 %0, {%1,%2};" : "=l"(r)
        : "r"(__float_as_uint(lo)), "r"(__float_as_uint(hi)));
    return r;
}
__device__ __forceinline__ void unpack2f(u64 v, float& lo, float& hi) {
    unsigned int a, b;
    asm("mov.b64 {%0,%1}, %2;" : "=r"(a), "=r"(b) : "l"(v));
    lo = __uint_as_float(a);
    hi = __uint_as_float(b);
}

__device__ __forceinline__ float sigm(float x) {
    return __fdividef(1.f, 1.f + __expf(-x));
}
__device__ __forceinline__ float tanh_(float x) {
    return __fdividef(2.f, 1.f + __expf(-2.f * x)) - 1.f;
}

// gate-major row j -> interleaved column
__device__ __forceinline__ int gcol(int j) {
    int g = j / HH, n = j - g * HH;
    return 4 * n + g;
}

// ---------------------------------------------------------------------------
// gx = X @ W^T + (b1 + b2), output layout [T][GP][B].
// XTB: X is [T][B][KK] (layer-0 input, transpose-stage) else [T][KK][B].
// CTA: 64 rows x 288 cols, 8 warps x 36 cols, 2 rows/lane.
// ---------------------------------------------------------------------------
template <int KK, bool XTB>
__global__ void __launch_bounds__(NTHR, 2)
gemm_x(const float* __restrict__ X, const float* __restrict__ W,
       const float* __restrict__ b1, const float* __restrict__ b2,
       float* __restrict__ gx)
{
    extern __shared__ float sm[];
    float* Wt   = sm;                 // [KK][GP]
    float* bias = Wt + KK * GP;       // [GP]
    float* xs   = bias + GP;          // [KK][69]

    const int tid  = threadIdx.x;
    const int lane = tid & 31;
    const int w    = tid >> 5;
    const int m0   = blockIdx.x * 64;
    const int t    = m0 >> 12;
    const int b0   = m0 & 4095;

    for (int i = tid; i < (KK + 1) * GP; i += NTHR) sm[i] = 0.f;
    __syncthreads();

    for (int idx = tid; idx < 4 * HH * KK; idx += NTHR) {
        int j = idx / KK, k = idx - j * KK;
        Wt[k * GP + gcol(j)] = W[idx];
    }
    for (int j = tid; j < 4 * HH; j += NTHR)
        bias[gcol(j)] = b1[j] + b2[j];

    if (XTB) {
        for (int idx = tid; idx < 64 * KK; idx += NTHR) {
            int r = idx / KK, k = idx - r * KK;
            xs[k * 69 + r] = X[((size_t)t * BB + b0 + r) * KK + k];
        }
    } else {
        for (int idx = tid; idx < 64 * KK; idx += NTHR) {
            int k = idx >> 6, r = idx & 63;
            xs[k * 69 + r] = X[((size_t)t * KK + k) * BB + b0 + r];
        }
    }
    __syncthreads();

    u64 a0[18], a1[18];
    {
        const ulonglong2* bp =
            reinterpret_cast<const ulonglong2*>(bias + w * 36);
#pragma unroll
        for (int q = 0; q < 9; q++) {
            ulonglong2 bv = bp[q];
            a0[2 * q] = bv.x;     a0[2 * q + 1] = bv.y;
            a1[2 * q] = bv.x;     a1[2 * q + 1] = bv.y;
        }
    }

    const float* Wrow = Wt + w * 36;
#pragma unroll 2
    for (int k = 0; k < KK; k++) {
        u64 x0 = dup2(xs[k * 69 + lane]);
        u64 x1 = dup2(xs[k * 69 + lane + 32]);
        const ulonglong2* Wk =
            reinterpret_cast<const ulonglong2*>(Wrow + k * GP);
#pragma unroll
        for (int q = 0; q < 9; q++) {
            ulonglong2 ww = Wk[q];
            FMA2A(a0[2 * q],     ww.x, x0);
            FMA2A(a0[2 * q + 1], ww.y, x0);
            FMA2A(a1[2 * q],     ww.x, x1);
            FMA2A(a1[2 * q + 1], ww.y, x1);
        }
    }

    float* gbase = gx + (size_t)t * GP * BB + b0;
#pragma unroll
    for (int q = 0; q < 18; q++) {
        int c0 = w * 36 + 2 * q;
        float lo, hi;
        unpack2f(a0[q], lo, hi);
        gbase[(size_t)c0 * BB + lane]       = lo;
        gbase[(size_t)(c0 + 1) * BB + lane] = hi;
        unpack2f(a1[q], lo, hi);
        gbase[(size_t)c0 * BB + lane + 32]       = lo;
        gbase[(size_t)(c0 + 1) * BB + lane + 32] = hi;
    }
}

// ---------------------------------------------------------------------------
// Recurrence: gates(t) = gx(t) + h(t-1) @ Whh^T, LSTM cell, k=70 only.
// ---------------------------------------------------------------------------
template <bool WRITE_SEQ>
__global__ void __launch_bounds__(NTHR, 1)
lstm_rec(const float* __restrict__ gx, const float* __restrict__ Whh,
         float* __restrict__ seq_out, float* __restrict__ fin_out)
{
    extern __shared__ float sm[];
    float* Wb = sm;                // [HH][GP]
    float* hb = Wb + HH * GP;      // [HH][33], undup

    const int tid  = threadIdx.x;
    const int lane = tid & 31;
    const int w    = tid >> 5;
    const int row0 = blockIdx.x * BC;

    for (int i = tid; i < HH * GP; i += NTHR) sm[i] = 0.f;
    for (int i = tid; i < HH * 33; i += NTHR) hb[i] = 0.f;
    __syncthreads();

    for (int idx = tid; idx < 4 * HH * HH; idx += NTHR) {
        int j = idx / HH, k = idx - j * HH;
        Wb[k * GP + gcol(j)] = Whh[idx];
    }
    __syncthreads();

    float creg[9];
#pragma unroll
    for (int u = 0; u < 9; u++) creg[u] = 0.f;

    // per-warp gx pointer: cols [36w, 36w+36), row row0+lane
    const float* gxw = gx + (size_t)(w * 36) * BB + row0 + lane;

    float cur[36], nxt[36];
#pragma unroll
    for (int j = 0; j < 36; j++)
        cur[j] = gxw[(size_t)j * BB];

    const float* Wrow = Wb + w * 36;

    for (int t = 0; t < TT; t++) {
        // gate accumulators initialized from gx
        u64 acc[18];
#pragma unroll
        for (int q = 0; q < 18; q++)
            acc[q] = pack2f(cur[2 * q], cur[2 * q + 1]);

        // prefetch next step's gx (independent of recurrence)
        if (t + 1 < TT) {
            const float* gn = gxw + (size_t)(t + 1) * GP * BB;
#pragma unroll
            for (int j = 0; j < 36; j++)
                nxt[j] = gn[(size_t)j * BB];
        }

        // recurrent GEMM, k = 70
#pragma unroll 2
        for (int k = 0; k < HH; k++) {
            u64 x2 = dup2(hb[k * 33 + lane]);
            const ulonglong2* Wk =
                reinterpret_cast<const ulonglong2*>(Wrow + k * GP);
#pragma unroll
            for (int q = 0; q < 9; q++) {
                ulonglong2 ww = Wk[q];
                FMA2A(acc[2 * q],     ww.x, x2);
                FMA2A(acc[2 * q + 1], ww.y, x2);
            }
        }
        __syncthreads();   // GEMM reads of hb done before overwrite

        // cell update: unit n = 9w+u, cols 4u..4u+3 = {i,f,g,o}
#pragma unroll
        for (int u = 0; u < 9; u++) {
            int n = 9 * w + u;
            float gi, gf, gg, go;
            unpack2f(acc[2 * u],     gi, gf);
            unpack2f(acc[2 * u + 1], gg, go);
            float iv = sigm(gi);
            float fv = sigm(gf);
            float gv = tanh_(gg);
            float ov = sigm(go);
            float c = __fmaf_rn(fv, creg[u], iv * gv);
            creg[u] = c;
            float h = ov * tanh_(c);
            if (n < HH) {
                hb[n * 33 + lane] = h;
                if (WRITE_SEQ)
                    seq_out[((size_t)t * HH + n) * BB + row0 + lane] = h;
                if (!WRITE_SEQ && t == TT - 1)
                    fin_out[n * BB + row0 + lane] = h;
            }
        }
        __syncthreads();   // hb ready for next step

#pragma unroll
        for (int j = 0; j < 36; j++) cur[j] = nxt[j];
    }
}

// head: out = sigmoid(relu(h1 @ W1.T + b1) @ W2.T + b2)
__global__ void __launch_bounds__(256)
head_kernel(const float* __restrict__ h1,  // [H][B]
            const float* __restrict__ W1, const float* __restrict__ b1,
            const float* __restrict__ W2, const float* __restrict__ b2,
            float* __restrict__ out)
{
    __shared__ float sW1[50 * HH];
    __shared__ float sb1[50];
    __shared__ float sW2[50];
    __shared__ float sb2;
    for (int i = threadIdx.x; i < 50 * HH; i += 256) sW1[i] = W1[i];
    if (threadIdx.x < 50) {
        sb1[threadIdx.x] = b1[threadIdx.x];
        sW2[threadIdx.x] = W2[threadIdx.x];
    }
    if (threadIdx.x == 0) sb2 = b2[0];
    __syncthreads();

    int row = blockIdx.x * 256 + threadIdx.x;
    float h[HH];
#pragma unroll
    for (int n = 0; n < HH; n++) h[n] = h1[n * BB + row];

    float o = sb2;
    for (int s = 0; s < 50; s++) {
        float a = sb1[s];
#pragma unroll
        for (int n = 0; n < HH; n++) a += h[n] * sW1[s * HH + n];
        a = fmaxf(a, 0.f);
        o += a * sW2[s];
    }
    out[row] = sigm(o);
}

extern "C" void kernel_launch(void* const* d_in, const int* in_sizes, int n_in,
                              void* d_out, int out_size)
{
    int o = (n_in >= 14 && in_sizes[1] == 1) ? 2 : 1;
    const float* data_in = (const float*)d_in[0];
    const float* W_ih0 = (const float*)d_in[o + 0];
    const float* W_hh0 = (const float*)d_in[o + 1];
    const float* b_ih0 = (const float*)d_in[o + 2];
    const float* b_hh0 = (const float*)d_in[o + 3];
    const float* W_ih1 = (const float*)d_in[o + 4];
    const float* W_hh1 = (const float*)d_in[o + 5];
    const float* b_ih1 = (const float*)d_in[o + 6];
    const float* b_hh1 = (const float*)d_in[o + 7];
    const float* W1    = (const float*)d_in[o + 8];
    const float* b1    = (const float*)d_in[o + 9];
    const float* W2    = (const float*)d_in[o + 10];
    const float* b2    = (const float*)d_in[o + 11];

    float *gxp = nullptr, *h0p = nullptr, *h1p = nullptr;
    cudaGetSymbolAddress((void**)&gxp, g_gx);
    cudaGetSymbolAddress((void**)&h0p, g_h0);
    cudaGetSymbolAddress((void**)&h1p, g_h1);

    const int smx0 = ((DD + 1) * GP + DD * 69) * 4;   // ~92.5 KB
    const int smx1 = ((HH + 1) * GP + HH * 69) * 4;   // ~101 KB
    const int smr  = (HH * GP + HH * 33) * 4;         // ~90 KB

    cudaFuncSetAttribute((const void*)gemm_x<DD, true>,
                         cudaFuncAttributeMaxDynamicSharedMemorySize, smx0);
    cudaFuncSetAttribute((const void*)gemm_x<HH, false>,
                         cudaFuncAttributeMaxDynamicSharedMemorySize, smx1);
    cudaFuncSetAttribute((const void*)lstm_rec<true>,
                         cudaFuncAttributeMaxDynamicSharedMemorySize, smr);
    cudaFuncSetAttribute((const void*)lstm_rec<false>,
                         cudaFuncAttributeMaxDynamicSharedMemorySize, smr);

    const int nx = (TT * BB) / 64;   // 32768 CTAs

    gemm_x<DD, true><<<nx, NTHR, smx0>>>(data_in, W_ih0, b_ih0, b_hh0, gxp);
    lstm_rec<true><<<NBLK, NTHR, smr>>>(gxp, W_hh0, h0p, nullptr);
    gemm_x<HH, false><<<nx, NTHR, smx1>>>(h0p, W_ih1, b_ih1, b_hh1, gxp);
    lstm_rec<false><<<NBLK, NTHR, smr>>>(gxp, W_hh1, nullptr, h1p);
    head_kernel<<<BB / 256, 256>>>(h1p, W1, b1, W2, b2, (float*)d_out);
}

// round 7
// speedup vs baseline: 1.2583x; 1.2583x over previous
#include <cuda_runtime.h>
#include <cstdint>
#include <cstddef>

// ---------------------------------------------------------------------------
// 2-layer LSTM (T=512, B=4096, D=64, H=70) + MLP head.
// R6: persistent gemm_x (weights staged once per CTA, grid-stride tiles);
//     recurrence unchanged from R5 (k=70 only, gx-streamed, MUFU acts).
// ---------------------------------------------------------------------------

#define TT   512
#define BB   4096
#define DD   64
#define HH   70
#define GP   288          // padded gate cols (4*72), col = 4n + gate
#define BC   32           // batch rows per recurrence CTA
#define NBLK (BB / BC)    // 128 blocks
#define NTHR 256
#define NPERS 296         // persistent gemm CTAs (2 per SM)

typedef unsigned long long u64;

// scratch: gate-x buffer [T][288][B] (reused for both layers),
//          h0 sequence [T][70][B], final h1 [70][B]
__device__ float g_gx[(size_t)TT * GP * BB];
__device__ float g_h0[(size_t)TT * HH * BB];
__device__ float g_h1[HH * BB];

#define FMA2A(d, a, b) \
    asm("fma.rn.f32x2 %0, %1, %2, %0;" : "+l"(d) : "l"(a), "l"(b))

__device__ __forceinline__ u64 dup2(float v) {
    u64 r;
    unsigned int u = __float_as_uint(v);
    asm("mov.b64 %0, {%1,%2};" : "=l"(r) : "r"(u), "r"(u));
    return r;
}
__device__ __forceinline__ u64 pack2f(float lo, float hi) {
    u64 r;
    asm("mov.b64 %0, {%1,%2};" : "=l"(r)
        : "r"(__float_as_uint(lo)), "r"(__float_as_uint(hi)));
    return r;
}
__device__ __forceinline__ void unpack2f(u64 v, float& lo, float& hi) {
    unsigned int a, b;
    asm("mov.b64 {%0,%1}, %2;" : "=r"(a), "=r"(b) : "l"(v));
    lo = __uint_as_float(a);
    hi = __uint_as_float(b);
}

__device__ __forceinline__ float sigm(float x) {
    return __fdividef(1.f, 1.f + __expf(-x));
}
__device__ __forceinline__ float tanh_(float x) {
    return __fdividef(2.f, 1.f + __expf(-2.f * x)) - 1.f;
}

// gate-major row j -> interleaved column
__device__ __forceinline__ int gcol(int j) {
    int g = j / HH, n = j - g * HH;
    return 4 * n + g;
}

// ---------------------------------------------------------------------------
// gx = X @ W^T + (b1 + b2), output layout [T][GP][B].
// Persistent: weights staged once, grid-stride over 64-row tiles.
// XTB: X is [T][B][KK] (layer-0 input) else [T][KK][B].
// ---------------------------------------------------------------------------
template <int KK, bool XTB>
__global__ void __launch_bounds__(NTHR, 2)
gemm_x(const float* __restrict__ X, const float* __restrict__ W,
       const float* __restrict__ b1, const float* __restrict__ b2,
       float* __restrict__ gx)
{
    extern __shared__ float sm[];
    float* Wt   = sm;                 // [KK][GP]
    float* bias = Wt + KK * GP;       // [GP]
    float* xs   = bias + GP;          // [KK][69]

    const int tid  = threadIdx.x;
    const int lane = tid & 31;
    const int w    = tid >> 5;

    // one-time weight stage (transpose + pad)
    for (int i = tid; i < (KK + 1) * GP; i += NTHR) sm[i] = 0.f;
    __syncthreads();
    for (int idx = tid; idx < 4 * HH * KK; idx += NTHR) {
        int j = idx / KK, k = idx - j * KK;
        Wt[k * GP + gcol(j)] = W[idx];
    }
    for (int j = tid; j < 4 * HH; j += NTHR)
        bias[gcol(j)] = b1[j] + b2[j];

    const ulonglong2* bp =
        reinterpret_cast<const ulonglong2*>(bias + w * 36);
    const float* Wrow = Wt + w * 36;

    const int ntiles = (TT * BB) / 64;
    for (int tile = blockIdx.x; tile < ntiles; tile += gridDim.x) {
        const int m0 = tile * 64;
        const int t  = m0 >> 12;
        const int b0 = m0 & 4095;

        __syncthreads();   // prior tile's xs reads complete
        if (XTB) {
#pragma unroll
            for (int ii = 0; ii < (64 * KK + NTHR - 1) / NTHR; ii++) {
                int idx = tid + ii * NTHR;
                if (idx < 64 * KK) {
                    int r = idx >> 6, k = idx & 63;
                    // consecutive idx -> consecutive k? need coalesced on X:
                    // X row-major [.., r, k]: use k-inner mapping
                    int kk = idx & 63, rr = idx >> 6;
                    (void)r; (void)k;
                    xs[kk * 69 + rr] =
                        X[((size_t)t * BB + b0 + rr) * KK + kk];
                }
            }
        } else {
#pragma unroll
            for (int ii = 0; ii < (64 * KK + NTHR - 1) / NTHR; ii++) {
                int idx = tid + ii * NTHR;
                if (idx < 64 * KK) {
                    int k = idx >> 6, r = idx & 63;
                    xs[k * 69 + r] =
                        X[((size_t)t * KK + k) * BB + b0 + r];
                }
            }
        }
        __syncthreads();

        u64 a0[18], a1[18];
#pragma unroll
        for (int q = 0; q < 9; q++) {
            ulonglong2 bv = bp[q];
            a0[2 * q] = bv.x;     a0[2 * q + 1] = bv.y;
            a1[2 * q] = bv.x;     a1[2 * q + 1] = bv.y;
        }

#pragma unroll 2
        for (int k = 0; k < KK; k++) {
            u64 x0 = dup2(xs[k * 69 + lane]);
            u64 x1 = dup2(xs[k * 69 + lane + 32]);
            const ulonglong2* Wk =
                reinterpret_cast<const ulonglong2*>(Wrow + k * GP);
#pragma unroll
            for (int q = 0; q < 9; q++) {
                ulonglong2 ww = Wk[q];
                FMA2A(a0[2 * q],     ww.x, x0);
                FMA2A(a0[2 * q + 1], ww.y, x0);
                FMA2A(a1[2 * q],     ww.x, x1);
                FMA2A(a1[2 * q + 1], ww.y, x1);
            }
        }

        float* gbase = gx + (size_t)t * GP * BB + b0;
#pragma unroll
        for (int q = 0; q < 18; q++) {
            int c0 = w * 36 + 2 * q;
            float lo, hi;
            unpack2f(a0[q], lo, hi);
            gbase[(size_t)c0 * BB + lane]       = lo;
            gbase[(size_t)(c0 + 1) * BB + lane] = hi;
            unpack2f(a1[q], lo, hi);
            gbase[(size_t)c0 * BB + lane + 32]       = lo;
            gbase[(size_t)(c0 + 1) * BB + lane + 32] = hi;
        }
    }
}

// ---------------------------------------------------------------------------
// Recurrence: gates(t) = gx(t) + h(t-1) @ Whh^T, LSTM cell, k=70 only.
// ---------------------------------------------------------------------------
template <bool WRITE_SEQ>
__global__ void __launch_bounds__(NTHR, 1)
lstm_rec(const float* __restrict__ gx, const float* __restrict__ Whh,
         float* __restrict__ seq_out, float* __restrict__ fin_out)
{
    extern __shared__ float sm[];
    float* Wb = sm;                // [HH][GP]
    float* hb = Wb + HH * GP;      // [HH][33]

    const int tid  = threadIdx.x;
    const int lane = tid & 31;
    const int w    = tid >> 5;
    const int row0 = blockIdx.x * BC;

    for (int i = tid; i < HH * GP; i += NTHR) sm[i] = 0.f;
    for (int i = tid; i < HH * 33; i += NTHR) hb[i] = 0.f;
    __syncthreads();

    for (int idx = tid; idx < 4 * HH * HH; idx += NTHR) {
        int j = idx / HH, k = idx - j * HH;
        Wb[k * GP + gcol(j)] = Whh[idx];
    }
    __syncthreads();

    float creg[9];
#pragma unroll
    for (int u = 0; u < 9; u++) creg[u] = 0.f;

    const float* gxw = gx + (size_t)(w * 36) * BB + row0 + lane;

    float cur[36], nxt[36];
#pragma unroll
    for (int j = 0; j < 36; j++)
        cur[j] = gxw[(size_t)j * BB];

    const float* Wrow = Wb + w * 36;

    for (int t = 0; t < TT; t++) {
        u64 acc[18];
#pragma unroll
        for (int q = 0; q < 18; q++)
            acc[q] = pack2f(cur[2 * q], cur[2 * q + 1]);

        if (t + 1 < TT) {
            const float* gn = gxw + (size_t)(t + 1) * GP * BB;
#pragma unroll
            for (int j = 0; j < 36; j++)
                nxt[j] = gn[(size_t)j * BB];
        }

#pragma unroll 2
        for (int k = 0; k < HH; k++) {
            u64 x2 = dup2(hb[k * 33 + lane]);
            const ulonglong2* Wk =
                reinterpret_cast<const ulonglong2*>(Wrow + k * GP);
#pragma unroll
            for (int q = 0; q < 9; q++) {
                ulonglong2 ww = Wk[q];
                FMA2A(acc[2 * q],     ww.x, x2);
                FMA2A(acc[2 * q + 1], ww.y, x2);
            }
        }
        __syncthreads();

#pragma unroll
        for (int u = 0; u < 9; u++) {
            int n = 9 * w + u;
            float gi, gf, gg, go;
            unpack2f(acc[2 * u],     gi, gf);
            unpack2f(acc[2 * u + 1], gg, go);
            float iv = sigm(gi);
            float fv = sigm(gf);
            float gv = tanh_(gg);
            float ov = sigm(go);
            float c = __fmaf_rn(fv, creg[u], iv * gv);
            creg[u] = c;
            float h = ov * tanh_(c);
            if (n < HH) {
                hb[n * 33 + lane] = h;
                if (WRITE_SEQ)
                    seq_out[((size_t)t * HH + n) * BB + row0 + lane] = h;
                if (!WRITE_SEQ && t == TT - 1)
                    fin_out[n * BB + row0 + lane] = h;
            }
        }
        __syncthreads();

#pragma unroll
        for (int j = 0; j < 36; j++) cur[j] = nxt[j];
    }
}

// head: out = sigmoid(relu(h1 @ W1.T + b1) @ W2.T + b2)
__global__ void __launch_bounds__(256)
head_kernel(const float* __restrict__ h1,  // [H][B]
            const float* __restrict__ W1, const float* __restrict__ b1,
            const float* __restrict__ W2, const float* __restrict__ b2,
            float* __restrict__ out)
{
    __shared__ float sW1[50 * HH];
    __shared__ float sb1[50];
    __shared__ float sW2[50];
    __shared__ float sb2;
    for (int i = threadIdx.x; i < 50 * HH; i += 256) sW1[i] = W1[i];
    if (threadIdx.x < 50) {
        sb1[threadIdx.x] = b1[threadIdx.x];
        sW2[threadIdx.x] = W2[threadIdx.x];
    }
    if (threadIdx.x == 0) sb2 = b2[0];
    __syncthreads();

    int row = blockIdx.x * 256 + threadIdx.x;
    float h[HH];
#pragma unroll
    for (int n = 0; n < HH; n++) h[n] = h1[n * BB + row];

    float o = sb2;
    for (int s = 0; s < 50; s++) {
        float a = sb1[s];
#pragma unroll
        for (int n = 0; n < HH; n++) a += h[n] * sW1[s * HH + n];
        a = fmaxf(a, 0.f);
        o += a * sW2[s];
    }
    out[row] = sigm(o);
}

extern "C" void kernel_launch(void* const* d_in, const int* in_sizes, int n_in,
                              void* d_out, int out_size)
{
    int o = (n_in >= 14 && in_sizes[1] == 1) ? 2 : 1;
    const float* data_in = (const float*)d_in[0];
    const float* W_ih0 = (const float*)d_in[o + 0];
    const float* W_hh0 = (const float*)d_in[o + 1];
    const float* b_ih0 = (const float*)d_in[o + 2];
    const float* b_hh0 = (const float*)d_in[o + 3];
    const float* W_ih1 = (const float*)d_in[o + 4];
    const float* W_hh1 = (const float*)d_in[o + 5];
    const float* b_ih1 = (const float*)d_in[o + 6];
    const float* b_hh1 = (const float*)d_in[o + 7];
    const float* W1    = (const float*)d_in[o + 8];
    const float* b1    = (const float*)d_in[o + 9];
    const float* W2    = (const float*)d_in[o + 10];
    const float* b2    = (const float*)d_in[o + 11];

    float *gxp = nullptr, *h0p = nullptr, *h1p = nullptr;
    cudaGetSymbolAddress((void**)&gxp, g_gx);
    cudaGetSymbolAddress((void**)&h0p, g_h0);
    cudaGetSymbolAddress((void**)&h1p, g_h1);

    const int smx0 = ((DD + 1) * GP + DD * 69) * 4;   // ~92.5 KB
    const int smx1 = ((HH + 1) * GP + HH * 69) * 4;   // ~101 KB
    const int smr  = (HH * GP + HH * 33) * 4;         // ~90 KB

    cudaFuncSetAttribute((const void*)gemm_x<DD, true>,
                         cudaFuncAttributeMaxDynamicSharedMemorySize, smx0);
    cudaFuncSetAttribute((const void*)gemm_x<HH, false>,
                         cudaFuncAttributeMaxDynamicSharedMemorySize, smx1);
    cudaFuncSetAttribute((const void*)lstm_rec<true>,
                         cudaFuncAttributeMaxDynamicSharedMemorySize, smr);
    cudaFuncSetAttribute((const void*)lstm_rec<false>,
                         cudaFuncAttributeMaxDynamicSharedMemorySize, smr);

    gemm_x<DD, true><<<NPERS, NTHR, smx0>>>(data_in, W_ih0, b_ih0, b_hh0, gxp);
    lstm_rec<true><<<NBLK, NTHR, smr>>>(gxp, W_hh0, h0p, nullptr);
    gemm_x<HH, false><<<NPERS, NTHR, smx1>>>(h0p, W_ih1, b_ih1, b_hh1, gxp);
    lstm_rec<false><<<NBLK, NTHR, smr>>>(gxp, W_hh1, nullptr, h1p);
    head_kernel<<<BB / 256, 256>>>(h1p, W1, b1, W2, b2, (float*)d_out);
}

// round 8
// speedup vs baseline: 1.3422x; 1.0667x over previous
#include <cuda_runtime.h>
#include <cstdint>
#include <cstddef>

// ---------------------------------------------------------------------------
// 2-layer LSTM (T=512, B=4096, D=64, H=70) + MLP head.
// R7: gemm_x with cp.async double-buffered input staging (persistent, 148
//     CTAs, 1/SM); lstm_rec with dup-u64 h state (LDS.64). MUFU activations.
// ---------------------------------------------------------------------------

#define TT   512
#define BB   4096
#define DD   64
#define HH   70
#define GP   288          // padded gate cols (4*72), col = 4n + gate
#define BC   32           // batch rows per recurrence CTA
#define NBLK (BB / BC)    // 128 blocks
#define NTHR 256
#define NPERS 148         // persistent gemm CTAs (1 per SM)

typedef unsigned long long u64;

// scratch: gate-x buffer [T][288][B] (reused for both layers),
//          h0 sequence [T][70][B], final h1 [70][B]
__device__ float g_gx[(size_t)TT * GP * BB];
__device__ float g_h0[(size_t)TT * HH * BB];
__device__ float g_h1[HH * BB];

#define FMA2A(d, a, b) \
    asm("fma.rn.f32x2 %0, %1, %2, %0;" : "+l"(d) : "l"(a), "l"(b))

#define CP16(dst_u32, src) \
    asm volatile("cp.async.ca.shared.global [%0], [%1], 16;" \
                 :: "r"(dst_u32), "l"(src))
#define CP_COMMIT() asm volatile("cp.async.commit_group;")
#define CP_WAIT0()  asm volatile("cp.async.wait_group 0;")
#define CP_WAIT1()  asm volatile("cp.async.wait_group 1;")

__device__ __forceinline__ u64 dup2(float v) {
    u64 r;
    unsigned int u = __float_as_uint(v);
    asm("mov.b64 %0, {%1,%2};" : "=l"(r) : "r"(u), "r"(u));
    return r;
}
__device__ __forceinline__ u64 pack2f(float lo, float hi) {
    u64 r;
    asm("mov.b64 %0, {%1,%2};" : "=l"(r)
        : "r"(__float_as_uint(lo)), "r"(__float_as_uint(hi)));
    return r;
}
__device__ __forceinline__ void unpack2f(u64 v, float& lo, float& hi) {
    unsigned int a, b;
    asm("mov.b64 {%0,%1}, %2;" : "=r"(a), "=r"(b) : "l"(v));
    lo = __uint_as_float(a);
    hi = __uint_as_float(b);
}

__device__ __forceinline__ float sigm(float x) {
    return __fdividef(1.f, 1.f + __expf(-x));
}
__device__ __forceinline__ float tanh_(float x) {
    return __fdividef(2.f, 1.f + __expf(-2.f * x)) - 1.f;
}

// gate-major row j -> interleaved column
__device__ __forceinline__ int gcol(int j) {
    int g = j / HH, n = j - g * HH;
    return 4 * n + g;
}

// ---------------------------------------------------------------------------
// gx = X @ W^T + (b1 + b2), output layout [T][GP][B].
// Persistent, cp.async double-buffered X staging.
// XTB: X is [T][B][KK] (layer-0 input) else [T][KK][B].
// ---------------------------------------------------------------------------
template <int KK, bool XTB>
__global__ void __launch_bounds__(NTHR, 1)
gemm_x(const float* __restrict__ X, const float* __restrict__ W,
       const float* __restrict__ b1, const float* __restrict__ b2,
       float* __restrict__ gx)
{
    // xs buffer geometry
    constexpr int XS_ELEMS = XTB ? (64 * 68) : (KK * 64);

    extern __shared__ float sm[];
    float* Wt   = sm;                 // [KK][GP]
    float* bias = Wt + KK * GP;       // [GP]
    float* xsA  = bias + GP;          // buffer 0
    float* xsB  = xsA + XS_ELEMS;     // buffer 1

    const int tid  = threadIdx.x;
    const int lane = tid & 31;
    const int w    = tid >> 5;

    // one-time weight stage (transpose + pad)
    for (int i = tid; i < (KK + 1) * GP; i += NTHR) sm[i] = 0.f;
    __syncthreads();
    for (int idx = tid; idx < 4 * HH * KK; idx += NTHR) {
        int j = idx / KK, k = idx - j * KK;
        Wt[k * GP + gcol(j)] = W[idx];
    }
    for (int j = tid; j < 4 * HH; j += NTHR)
        bias[gcol(j)] = b1[j] + b2[j];
    __syncthreads();

    const ulonglong2* bp =
        reinterpret_cast<const ulonglong2*>(bias + w * 36);
    const float* Wrow = Wt + w * 36;

    const int ntiles = (TT * BB) / 64;

    // stage a tile into buf via cp.async (16B chunks)
    auto stage = [&](int tile, float* buf) {
        const int m0 = tile * 64;
        const int t  = m0 >> 12;
        const int b0 = m0 & 4095;
        if (XTB) {
            // X [T][B][KK=64]: row r contiguous in k; swizzled [r][68] layout
#pragma unroll
            for (int ii = 0; ii < (64 * 16) / NTHR; ii++) {
                int idx = tid + ii * NTHR;
                int r = idx >> 4, c = idx & 15;
                int cs = c ^ ((r >> 3) & 3);
                const float* src = X + ((size_t)t * BB + b0 + r) * KK + c * 4;
                uint32_t dst = (uint32_t)__cvta_generic_to_shared(
                    buf + r * 68 + cs * 4);
                CP16(dst, src);
            }
        } else {
            // X [T][KK][B]: k-row contiguous in batch; [k][64] layout
#pragma unroll
            for (int ii = 0; ii < (KK * 16 + NTHR - 1) / NTHR; ii++) {
                int idx = tid + ii * NTHR;
                if (idx < KK * 16) {
                    int k = idx >> 4, c = idx & 15;
                    const float* src = X + ((size_t)t * KK + k) * BB + b0 + c * 4;
                    uint32_t dst = (uint32_t)__cvta_generic_to_shared(
                        buf + k * 64 + c * 4);
                    CP16(dst, src);
                }
            }
        }
        CP_COMMIT();
    };

    int myfirst = blockIdx.x;
    if (myfirst < ntiles) stage(myfirst, xsA);

    int bufsel = 0;
    for (int tile = myfirst; tile < ntiles; tile += gridDim.x) {
        float* cur = bufsel ? xsB : xsA;
        float* nxt = bufsel ? xsA : xsB;

        __syncthreads();   // everyone done reading `nxt`'s previous contents
        bool hasnext = (tile + gridDim.x) < ntiles;
        if (hasnext) {
            stage(tile + gridDim.x, nxt);
            CP_WAIT1();    // current buffer's group complete
        } else {
            CP_WAIT0();
        }
        __syncthreads();   // cur visible to all threads

        const int m0 = tile * 64;
        const int t  = m0 >> 12;
        const int b0 = m0 & 4095;

        u64 a0[18], a1[18];
#pragma unroll
        for (int q = 0; q < 9; q++) {
            ulonglong2 bv = bp[q];
            a0[2 * q] = bv.x;     a0[2 * q + 1] = bv.y;
            a1[2 * q] = bv.x;     a1[2 * q + 1] = bv.y;
        }

        if (XTB) {
            const int base0 = lane * 68;
            const int xorp  = (lane >> 3) & 3;
#pragma unroll 2
            for (int k = 0; k < KK; k++) {
                int sw = (((k >> 2) ^ xorp) << 2) + (k & 3);
                u64 x0 = dup2(cur[base0 + sw]);
                u64 x1 = dup2(cur[base0 + 32 * 68 + sw]);
                const ulonglong2* Wk =
                    reinterpret_cast<const ulonglong2*>(Wrow + k * GP);
#pragma unroll
                for (int q = 0; q < 9; q++) {
                    ulonglong2 ww = Wk[q];
                    FMA2A(a0[2 * q],     ww.x, x0);
                    FMA2A(a0[2 * q + 1], ww.y, x0);
                    FMA2A(a1[2 * q],     ww.x, x1);
                    FMA2A(a1[2 * q + 1], ww.y, x1);
                }
            }
        } else {
#pragma unroll 2
            for (int k = 0; k < KK; k++) {
                u64 x0 = dup2(cur[k * 64 + lane]);
                u64 x1 = dup2(cur[k * 64 + lane + 32]);
                const ulonglong2* Wk =
                    reinterpret_cast<const ulonglong2*>(Wrow + k * GP);
#pragma unroll
                for (int q = 0; q < 9; q++) {
                    ulonglong2 ww = Wk[q];
                    FMA2A(a0[2 * q],     ww.x, x0);
                    FMA2A(a0[2 * q + 1], ww.y, x0);
                    FMA2A(a1[2 * q],     ww.x, x1);
                    FMA2A(a1[2 * q + 1], ww.y, x1);
                }
            }
        }

        float* gbase = gx + (size_t)t * GP * BB + b0;
#pragma unroll
        for (int q = 0; q < 18; q++) {
            int c0 = w * 36 + 2 * q;
            float lo, hi;
            unpack2f(a0[q], lo, hi);
            gbase[(size_t)c0 * BB + lane]       = lo;
            gbase[(size_t)(c0 + 1) * BB + lane] = hi;
            unpack2f(a1[q], lo, hi);
            gbase[(size_t)c0 * BB + lane + 32]       = lo;
            gbase[(size_t)(c0 + 1) * BB + lane + 32] = hi;
        }

        bufsel ^= 1;
    }
}

// ---------------------------------------------------------------------------
// Recurrence: gates(t) = gx(t) + h(t-1) @ Whh^T, LSTM cell, k=70 only.
// ---------------------------------------------------------------------------
template <bool WRITE_SEQ>
__global__ void __launch_bounds__(NTHR, 1)
lstm_rec(const float* __restrict__ gx, const float* __restrict__ Whh,
         float* __restrict__ seq_out, float* __restrict__ fin_out)
{
    extern __shared__ float sm[];
    float* Wb = sm;                                   // [HH][GP]
    u64*   hb = reinterpret_cast<u64*>(Wb + HH * GP); // [HH][33] dup pairs

    const int tid  = threadIdx.x;
    const int lane = tid & 31;
    const int w    = tid >> 5;
    const int row0 = blockIdx.x * BC;

    for (int i = tid; i < HH * GP; i += NTHR) sm[i] = 0.f;
    {
        float* hf = reinterpret_cast<float*>(hb);
        for (int i = tid; i < HH * 33 * 2; i += NTHR) hf[i] = 0.f;
    }
    __syncthreads();

    for (int idx = tid; idx < 4 * HH * HH; idx += NTHR) {
        int j = idx / HH, k = idx - j * HH;
        Wb[k * GP + gcol(j)] = Whh[idx];
    }
    __syncthreads();

    float creg[9];
#pragma unroll
    for (int u = 0; u < 9; u++) creg[u] = 0.f;

    const float* gxw = gx + (size_t)(w * 36) * BB + row0 + lane;

    float cur[36], nxt[36];
#pragma unroll
    for (int j = 0; j < 36; j++)
        cur[j] = gxw[(size_t)j * BB];

    const float* Wrow = Wb + w * 36;

    for (int t = 0; t < TT; t++) {
        u64 acc[18];
#pragma unroll
        for (int q = 0; q < 18; q++)
            acc[q] = pack2f(cur[2 * q], cur[2 * q + 1]);

        if (t + 1 < TT) {
            const float* gn = gxw + (size_t)(t + 1) * GP * BB;
#pragma unroll
            for (int j = 0; j < 36; j++)
                nxt[j] = gn[(size_t)j * BB];
        }

        const u64* hp = hb + lane;
#pragma unroll 2
        for (int k = 0; k < HH; k++) {
            u64 x2 = hp[k * 33];
            const ulonglong2* Wk =
                reinterpret_cast<const ulonglong2*>(Wrow + k * GP);
#pragma unroll
            for (int q = 0; q < 9; q++) {
                ulonglong2 ww = Wk[q];
                FMA2A(acc[2 * q],     ww.x, x2);
                FMA2A(acc[2 * q + 1], ww.y, x2);
            }
        }
        __syncthreads();

#pragma unroll
        for (int u = 0; u < 9; u++) {
            int n = 9 * w + u;
            float gi, gf, gg, go;
            unpack2f(acc[2 * u],     gi, gf);
            unpack2f(acc[2 * u + 1], gg, go);
            float iv = sigm(gi);
            float fv = sigm(gf);
            float gv = tanh_(gg);
            float ov = sigm(go);
            float c = __fmaf_rn(fv, creg[u], iv * gv);
            creg[u] = c;
            float h = ov * tanh_(c);
            if (n < HH) {
                hb[n * 33 + lane] = dup2(h);
                if (WRITE_SEQ)
                    seq_out[((size_t)t * HH + n) * BB + row0 + lane] = h;
                if (!WRITE_SEQ && t == TT - 1)
                    fin_out[n * BB + row0 + lane] = h;
            }
        }
        __syncthreads();

#pragma unroll
        for (int j = 0; j < 36; j++) cur[j] = nxt[j];
    }
}

// head: out = sigmoid(relu(h1 @ W1.T + b1) @ W2.T + b2)
__global__ void __launch_bounds__(256)
head_kernel(const float* __restrict__ h1,  // [H][B]
            const float* __restrict__ W1, const float* __restrict__ b1,
            const float* __restrict__ W2, const float* __restrict__ b2,
            float* __restrict__ out)
{
    __shared__ float sW1[50 * HH];
    __shared__ float sb1[50];
    __shared__ float sW2[50];
    __shared__ float sb2;
    for (int i = threadIdx.x; i < 50 * HH; i += 256) sW1[i] = W1[i];
    if (threadIdx.x < 50) {
        sb1[threadIdx.x] = b1[threadIdx.x];
        sW2[threadIdx.x] = W2[threadIdx.x];
    }
    if (threadIdx.x == 0) sb2 = b2[0];
    __syncthreads();

    int row = blockIdx.x * 256 + threadIdx.x;
    float h[HH];
#pragma unroll
    for (int n = 0; n < HH; n++) h[n] = h1[n * BB + row];

    float o = sb2;
    for (int s = 0; s < 50; s++) {
        float a = sb1[s];
#pragma unroll
        for (int n = 0; n < HH; n++) a += h[n] * sW1[s * HH + n];
        a = fmaxf(a, 0.f);
        o += a * sW2[s];
    }
    out[row] = sigm(o);
}

extern "C" void kernel_launch(void* const* d_in, const int* in_sizes, int n_in,
                              void* d_out, int out_size)
{
    int o = (n_in >= 14 && in_sizes[1] == 1) ? 2 : 1;
    const float* data_in = (const float*)d_in[0];
    const float* W_ih0 = (const float*)d_in[o + 0];
    const float* W_hh0 = (const float*)d_in[o + 1];
    const float* b_ih0 = (const float*)d_in[o + 2];
    const float* b_hh0 = (const float*)d_in[o + 3];
    const float* W_ih1 = (const float*)d_in[o + 4];
    const float* W_hh1 = (const float*)d_in[o + 5];
    const float* b_ih1 = (const float*)d_in[o + 6];
    const float* b_hh1 = (const float*)d_in[o + 7];
    const float* W1    = (const float*)d_in[o + 8];
    const float* b1    = (const float*)d_in[o + 9];
    const float* W2    = (const float*)d_in[o + 10];
    const float* b2    = (const float*)d_in[o + 11];

    float *gxp = nullptr, *h0p = nullptr, *h1p = nullptr;
    cudaGetSymbolAddress((void**)&gxp, g_gx);
    cudaGetSymbolAddress((void**)&h0p, g_h0);
    cudaGetSymbolAddress((void**)&h1p, g_h1);

    const int smx0 = ((DD + 1) * GP) * 4 + 2 * (64 * 68) * 4;   // ~109 KB
    const int smx1 = ((HH + 1) * GP) * 4 + 2 * (HH * 64) * 4;   // ~117 KB
    const int smr  = (HH * GP) * 4 + HH * 33 * 8;               // ~99 KB

    cudaFuncSetAttribute((const void*)gemm_x<DD, true>,
                         cudaFuncAttributeMaxDynamicSharedMemorySize, smx0);
    cudaFuncSetAttribute((const void*)gemm_x<HH, false>,
                         cudaFuncAttributeMaxDynamicSharedMemorySize, smx1);
    cudaFuncSetAttribute((const void*)lstm_rec<true>,
                         cudaFuncAttributeMaxDynamicSharedMemorySize, smr);
    cudaFuncSetAttribute((const void*)lstm_rec<false>,
                         cudaFuncAttributeMaxDynamicSharedMemorySize, smr);

    gemm_x<DD, true><<<NPERS, NTHR, smx0>>>(data_in, W_ih0, b_ih0, b_hh0, gxp);
    lstm_rec<true><<<NBLK, NTHR, smr>>>(gxp, W_hh0, h0p, nullptr);
    gemm_x<HH, false><<<NPERS, NTHR, smx1>>>(h0p, W_ih1, b_ih1, b_hh1, gxp);
    lstm_rec<false><<<NBLK, NTHR, smr>>>(gxp, W_hh1, nullptr, h1p);
    head_kernel<<<BB / 256, 256>>>(h1p, W1, b1, W2, b2, (float*)d_out);
}